// round 3
// baseline (speedup 1.0000x reference)
#include <cuda_runtime.h>
#include <cuda_bf16.h>

#define MAX_BLOCKS 4096

// Scratch (no allocations allowed): per-block partials + completion ticket.
// g_partials slots are overwritten unconditionally each run; g_count is
// returned to 0 by the last block, so replays are deterministic.
__device__ float        g_partials[MAX_BLOCKS];
__device__ unsigned int g_count = 0;

__global__ void __launch_bounds__(256, 8) wmse_fused_kernel(
    const float4* __restrict__ pred4,
    const int4*   __restrict__ lab4,
    const float*  __restrict__ weights,
    float*        __restrict__ out,
    int nvec, float inv_n)
{
    __shared__ float sw[16];
    __shared__ float warp_sums[8];
    __shared__ int   s_last;

    if (threadIdx.x < 10) sw[threadIdx.x] = weights[threadIdx.x];
    __syncthreads();

    // ---- grid-stride main loop: 2x LDG.128 per iteration, unrolled 4x ----
    float acc = 0.0f;
    int i = blockIdx.x * blockDim.x + threadIdx.x;
    const int stride = gridDim.x * blockDim.x;

    #pragma unroll 4
    for (; i < nvec; i += stride) {
        float4 p = pred4[i];
        int4   l = lab4[i];
        float d0 = p.x - (float)l.x;
        float d1 = p.y - (float)l.y;
        float d2 = p.z - (float)l.z;
        float d3 = p.w - (float)l.w;
        acc = fmaf(sw[l.x] * d0, d0, acc);
        acc = fmaf(sw[l.y] * d1, d1, acc);
        acc = fmaf(sw[l.z] * d2, d2, acc);
        acc = fmaf(sw[l.w] * d3, d3, acc);
    }

    // ---- block reduction ----
    #pragma unroll
    for (int off = 16; off > 0; off >>= 1)
        acc += __shfl_down_sync(0xFFFFFFFFu, acc, off);

    const int warp = threadIdx.x >> 5;
    const int lane = threadIdx.x & 31;
    if (lane == 0) warp_sums[warp] = acc;
    __syncthreads();

    if (warp == 0) {
        acc = (lane < 8) ? warp_sums[lane] : 0.0f;
        #pragma unroll
        for (int off = 4; off > 0; off >>= 1)
            acc += __shfl_down_sync(0xFFFFFFFFu, acc, off);
    }

    // ---- last-block finalize (threadfence reduction) ----
    if (threadIdx.x == 0) {
        g_partials[blockIdx.x] = acc;
        __threadfence();
        unsigned int ticket = atomicAdd(&g_count, 1u);
        s_last = (ticket == gridDim.x - 1) ? 1 : 0;
    }
    __syncthreads();

    if (s_last) {
        float v = 0.0f;
        for (int j = threadIdx.x; j < gridDim.x; j += blockDim.x)
            v += g_partials[j];

        #pragma unroll
        for (int off = 16; off > 0; off >>= 1)
            v += __shfl_down_sync(0xFFFFFFFFu, v, off);
        if (lane == 0) warp_sums[warp] = v;
        __syncthreads();
        if (warp == 0) {
            v = (lane < 8) ? warp_sums[lane] : 0.0f;
            #pragma unroll
            for (int off = 4; off > 0; off >>= 1)
                v += __shfl_down_sync(0xFFFFFFFFu, v, off);
            if (lane == 0) {
                out[0] = v * inv_n;
                g_count = 0;   // reset for next graph replay
            }
        }
    }
}

extern "C" void kernel_launch(void* const* d_in, const int* in_sizes, int n_in,
                              void* d_out, int out_size) {
    const float* predictions = (const float*)d_in[0];
    const int*   labels      = (const int*)d_in[1];
    const float* weights     = (const float*)d_in[2];
    float*       out         = (float*)d_out;

    const long long n = (long long)in_sizes[0];   // 33,554,432 (divisible by 4)
    const int nvec = (int)(n >> 2);               // 8,388,608 vec4 elements

    // Single full-occupancy wave: 152 SMs * 8 blocks of 256 threads.
    int grid = 152 * 8;                           // 1216 <= MAX_BLOCKS
    const int block = 256;

    wmse_fused_kernel<<<grid, block>>>(
        (const float4*)predictions, (const int4*)labels, weights, out,
        nvec, 1.0f / (float)n);
}